// round 1
// baseline (speedup 1.0000x reference)
#include <cuda_runtime.h>
#include <cuda_bf16.h>
#include <math.h>

// Problem constants
#define S_LEN  2048
#define HID    2048
#define NH     16
#define NKV    4
#define HD     128          // head dim
#define KVDIM  512          // NKV * HD
#define QKVW   3072         // 2048 + 512 + 512

// Scratch (device globals — no allocation allowed)
__device__ float g_qkv[S_LEN * QKVW];     // [S][3072]: Q | K | V
__device__ float g_attn[S_LEN * HID];     // attention output [S][2048]

// ---------------------------------------------------------------------------
// SGEMM: C[m, coff+n] = sum_k A[m,k] * B[n,k]   (A: MxK row-major, B: NxK row-major)
// BM=BN=128, BK=8, 256 threads, 8x8 microtile. M,N,K multiples of 128 (N mult of 128).
// ---------------------------------------------------------------------------
__global__ __launch_bounds__(256, 2)
void sgemm_nt(const float* __restrict__ A, const float* __restrict__ B,
              float* __restrict__ C, int M, int N, int K, int ldc, int coff) {
    __shared__ float As[8][128];
    __shared__ float Bs[8][128];

    const int tid = threadIdx.x;
    const int bm = blockIdx.y * 128;
    const int bn = blockIdx.x * 128;
    const int tr = tid >> 4;          // 0..15
    const int tc = tid & 15;          // 0..15

    const int lr = tid >> 1;          // 0..127
    const int lc = (tid & 1) << 2;    // 0 or 4

    float acc[8][8];
#pragma unroll
    for (int i = 0; i < 8; i++)
#pragma unroll
        for (int j = 0; j < 8; j++) acc[i][j] = 0.f;

    const float* Aptr = A + (size_t)(bm + lr) * K + lc;
    const float* Bptr = B + (size_t)(bn + lr) * K + lc;

    for (int k0 = 0; k0 < K; k0 += 8) {
        float4 av = *(const float4*)(Aptr + k0);
        float4 bv = *(const float4*)(Bptr + k0);
        As[lc + 0][lr] = av.x; As[lc + 1][lr] = av.y;
        As[lc + 2][lr] = av.z; As[lc + 3][lr] = av.w;
        Bs[lc + 0][lr] = bv.x; Bs[lc + 1][lr] = bv.y;
        Bs[lc + 2][lr] = bv.z; Bs[lc + 3][lr] = bv.w;
        __syncthreads();

#pragma unroll
        for (int kk = 0; kk < 8; kk++) {
            float a[8], b[8];
            *(float4*)&a[0] = *(const float4*)&As[kk][tr * 8];
            *(float4*)&a[4] = *(const float4*)&As[kk][tr * 8 + 4];
            *(float4*)&b[0] = *(const float4*)&Bs[kk][tc * 8];
            *(float4*)&b[4] = *(const float4*)&Bs[kk][tc * 8 + 4];
#pragma unroll
            for (int i = 0; i < 8; i++)
#pragma unroll
                for (int j = 0; j < 8; j++) acc[i][j] += a[i] * b[j];
        }
        __syncthreads();
    }

#pragma unroll
    for (int i = 0; i < 8; i++) {
        float* crow = C + (size_t)(bm + tr * 8 + i) * ldc + coff + bn + tc * 8;
#pragma unroll
        for (int j = 0; j < 8; j += 4) {
            float4 v = make_float4(acc[i][j], acc[i][j+1], acc[i][j+2], acc[i][j+3]);
            *(float4*)(crow + j) = v;
        }
    }
}

// ---------------------------------------------------------------------------
// RoPE in-place on g_qkv. grid (S, NH+NKV), block 64 (one thread per freq pair)
// ---------------------------------------------------------------------------
__global__ void rope_kernel(float* __restrict__ qkv) {
    const int s = blockIdx.x;
    const int h = blockIdx.y;               // 0..19 (16 q heads then 4 kv heads)
    const int i = threadIdx.x;              // 0..63
    const int col = (h < NH) ? h * HD : (HID + (h - NH) * HD);
    float* p = qkv + (size_t)s * QKVW + col;

    // inv_freq = ROPE_BASE^(-2i/d)
    float ang = (float)s * powf(10000.0f, -(float)(2 * i) / (float)HD);
    float c = cosf(ang), sn = sinf(ang);
    float x0 = p[i], x1 = p[i + 64];
    p[i]      = x0 * c - x1 * sn;
    p[i + 64] = x1 * c + x0 * sn;
}

// ---------------------------------------------------------------------------
// Flash attention (causal, GQA). One CTA per (q-block of 64, head).
// BM=BN=64, D=128, 256 threads. fp32 everywhere, online softmax.
// smem (floats): Qt[128][68] | Kt[128][68] | Vs[64][132] | Pt[64][68] | m,l,sc[64]
// ---------------------------------------------------------------------------
#define FA_SMEM_FLOATS (128*68 + 128*68 + 64*132 + 64*68 + 192)

__global__ __launch_bounds__(256, 1)
void flash_attn_kernel(const float* __restrict__ qkv, float* __restrict__ attn_out) {
    extern __shared__ float sm[];
    float* Qt   = sm;                       // [128][68] (k-major transposed)
    float* Kt   = Qt + 128 * 68;            // [128][68]
    float* Vs   = Kt + 128 * 68;            // [64][132] row-major
    float* Pt   = Vs + 64 * 132;            // [64][68]  (col-major scores/probs)
    float* mrow = Pt + 64 * 68;             // [64]
    float* lrow = mrow + 64;                // [64]
    float* srow = lrow + 64;                // [64]

    const int qb  = blockIdx.x;             // 0..31
    const int h   = blockIdx.y;             // 0..15
    const int tid = threadIdx.x;
    const int tr  = tid >> 4;               // 0..15
    const int tc  = tid & 15;               // 0..15
    const int kvh = h >> 2;
    const int q_col0 = h * HD;
    const int k_col0 = HID + kvh * HD;
    const int v_col0 = HID + KVDIM + kvh * HD;
    const int q_row0 = qb * 64;

    // Load Q tile transposed: Qt[c][r]
    for (int idx = tid; idx < 64 * 32; idx += 256) {
        int r = idx >> 5, c4 = (idx & 31) << 2;
        float4 v = *(const float4*)&qkv[(size_t)(q_row0 + r) * QKVW + q_col0 + c4];
        Qt[(c4 + 0) * 68 + r] = v.x;
        Qt[(c4 + 1) * 68 + r] = v.y;
        Qt[(c4 + 2) * 68 + r] = v.z;
        Qt[(c4 + 3) * 68 + r] = v.w;
    }
    if (tid < 64) { mrow[tid] = -INFINITY; lrow[tid] = 0.f; }

    float o_acc[4][8];
#pragma unroll
    for (int i = 0; i < 4; i++)
#pragma unroll
        for (int j = 0; j < 8; j++) o_acc[i][j] = 0.f;

    const float sscale = 0.08838834764831845f;   // 1/sqrt(128)

    for (int kb = 0; kb <= qb; kb++) {
        __syncthreads();   // previous iter consumers done before overwrite
        // Load K (transposed) and V tiles
        for (int idx = tid; idx < 64 * 32; idx += 256) {
            int r = idx >> 5, c4 = (idx & 31) << 2;
            size_t rowoff = (size_t)(kb * 64 + r) * QKVW;
            float4 kv4 = *(const float4*)&qkv[rowoff + k_col0 + c4];
            Kt[(c4 + 0) * 68 + r] = kv4.x;
            Kt[(c4 + 1) * 68 + r] = kv4.y;
            Kt[(c4 + 2) * 68 + r] = kv4.z;
            Kt[(c4 + 3) * 68 + r] = kv4.w;
            float4 vv = *(const float4*)&qkv[rowoff + v_col0 + c4];
            *(float4*)&Vs[r * 132 + c4] = vv;
        }
        __syncthreads();

        // Scores S = Q K^T (4x4 microtile per thread)
        float acc[4][4];
#pragma unroll
        for (int i = 0; i < 4; i++)
#pragma unroll
            for (int j = 0; j < 4; j++) acc[i][j] = 0.f;

#pragma unroll 4
        for (int kk = 0; kk < 128; kk++) {
            float a[4], b[4];
            *(float4*)a = *(const float4*)&Qt[kk * 68 + tr * 4];
            *(float4*)b = *(const float4*)&Kt[kk * 68 + tc * 4];
#pragma unroll
            for (int i = 0; i < 4; i++)
#pragma unroll
                for (int j = 0; j < 4; j++) acc[i][j] += a[i] * b[j];
        }

        // Mask + scale, write to Pt (column-major)
        const bool diag = (kb == qb);
#pragma unroll
        for (int i = 0; i < 4; i++) {
            int grow = q_row0 + tr * 4 + i;
#pragma unroll
            for (int j = 0; j < 4; j++) {
                int gcol = kb * 64 + tc * 4 + j;
                float s = acc[i][j] * sscale;
                if (diag && gcol > grow) s = -1e30f;
                Pt[(tc * 4 + j) * 68 + (tr * 4 + i)] = s;
            }
        }
        __syncthreads();

        // Online softmax: 4 threads per row
        {
            int row = tid >> 2, qd = tid & 3;
            float vals[16];
            float lmax = -1e30f;
#pragma unroll
            for (int jj = 0; jj < 16; jj++) {
                vals[jj] = Pt[(qd * 16 + jj) * 68 + row];
                lmax = fmaxf(lmax, vals[jj]);
            }
            lmax = fmaxf(lmax, __shfl_xor_sync(0xffffffffu, lmax, 1));
            lmax = fmaxf(lmax, __shfl_xor_sync(0xffffffffu, lmax, 2));
            float m_old = mrow[row];
            float m_new = fmaxf(m_old, lmax);
            float psum = 0.f;
#pragma unroll
            for (int jj = 0; jj < 16; jj++) {
                float p = __expf(vals[jj] - m_new);
                Pt[(qd * 16 + jj) * 68 + row] = p;
                psum += p;
            }
            psum += __shfl_xor_sync(0xffffffffu, psum, 1);
            psum += __shfl_xor_sync(0xffffffffu, psum, 2);
            if (qd == 0) {
                float sc = __expf(m_old - m_new);
                srow[row] = sc;
                mrow[row] = m_new;
                lrow[row] = lrow[row] * sc + psum;
            }
        }
        __syncthreads();

        // Rescale accumulator
#pragma unroll
        for (int i = 0; i < 4; i++) {
            float sc = srow[tr * 4 + i];
#pragma unroll
            for (int j = 0; j < 8; j++) o_acc[i][j] *= sc;
        }

        // O += P @ V (4x8 microtile per thread)
#pragma unroll 4
        for (int kk = 0; kk < 64; kk++) {
            float a[4], b[8];
            *(float4*)a = *(const float4*)&Pt[kk * 68 + tr * 4];
            *(float4*)&b[0] = *(const float4*)&Vs[kk * 132 + tc * 8];
            *(float4*)&b[4] = *(const float4*)&Vs[kk * 132 + tc * 8 + 4];
#pragma unroll
            for (int i = 0; i < 4; i++)
#pragma unroll
                for (int j = 0; j < 8; j++) o_acc[i][j] += a[i] * b[j];
        }
    }

    // Epilogue: normalize and write [S][2048]
#pragma unroll
    for (int i = 0; i < 4; i++) {
        float inv = 1.0f / lrow[tr * 4 + i];
        float* orow = attn_out + (size_t)(q_row0 + tr * 4 + i) * HID + h * HD + tc * 8;
#pragma unroll
        for (int j = 0; j < 8; j += 4) {
            float4 v = make_float4(o_acc[i][j] * inv, o_acc[i][j+1] * inv,
                                   o_acc[i][j+2] * inv, o_acc[i][j+3] * inv);
            *(float4*)(orow + j) = v;
        }
    }
}

// ---------------------------------------------------------------------------
extern "C" void kernel_launch(void* const* d_in, const int* in_sizes, int n_in,
                              void* d_out, int out_size) {
    const float* X  = (const float*)d_in[0];   // [2048,2048]
    const float* Wq = (const float*)d_in[1];   // [2048,2048]
    const float* Wk = (const float*)d_in[2];   // [512,2048]
    const float* Wv = (const float*)d_in[3];   // [512,2048]
    const float* Wo = (const float*)d_in[4];   // [2048,2048]
    float* out = (float*)d_out;

    void* p;
    cudaGetSymbolAddress(&p, g_qkv);
    float* qkv = (float*)p;
    cudaGetSymbolAddress(&p, g_attn);
    float* attn = (float*)p;

    const size_t fa_smem = FA_SMEM_FLOATS * sizeof(float);
    cudaFuncSetAttribute(flash_attn_kernel,
                         cudaFuncAttributeMaxDynamicSharedMemorySize, (int)fa_smem);

    dim3 blk(256);
    // Q/K/V projections into fused qkv buffer
    sgemm_nt<<<dim3(16, 16), blk>>>(X, Wq, qkv, S_LEN, HID,   HID, QKVW, 0);
    sgemm_nt<<<dim3(4, 16),  blk>>>(X, Wk, qkv, S_LEN, KVDIM, HID, QKVW, HID);
    sgemm_nt<<<dim3(4, 16),  blk>>>(X, Wv, qkv, S_LEN, KVDIM, HID, QKVW, HID + KVDIM);

    // RoPE on Q and K
    rope_kernel<<<dim3(S_LEN, NH + NKV), 64>>>(qkv);

    // Causal GQA flash attention
    flash_attn_kernel<<<dim3(S_LEN / 64, NH), blk, fa_smem>>>(qkv, attn);

    // Output projection
    sgemm_nt<<<dim3(16, 16), blk>>>(attn, Wo, out, S_LEN, HID, HID, HID, 0);
}

// round 3
// speedup vs baseline: 1.8272x; 1.8272x over previous
#include <cuda_runtime.h>
#include <cuda_bf16.h>
#include <math.h>
#include <stdint.h>

// Problem constants
#define S_LEN  2048
#define HID    2048
#define NH     16
#define NKV    4
#define HD     128
#define KVDIM  512
#define QKVW   3072
#define K0     2048
#define KC     (3*K0)      // 6144 split-bf16 concatenated K

// Scratch (device globals — no allocation allowed)
__device__ float g_qkv[S_LEN * QKVW];            // [S][3072]: Q | K | V (fp32)
__device__ float g_attn[S_LEN * HID];            // attention output (fp32)
__device__ __nv_bfloat16 g_Xc[S_LEN * KC];       // X split-cat  [2048,6144]
__device__ __nv_bfloat16 g_Wqkvc[QKVW * KC];     // Wq|Wk|Wv split-cat [3072,6144]
__device__ __nv_bfloat16 g_Woc[HID * KC];        // Wo split-cat [2048,6144]
__device__ __nv_bfloat16 g_attnc[S_LEN * KC];    // attn split-cat

// ---------------------------------------------------------------------------
// helpers
// ---------------------------------------------------------------------------
__device__ __forceinline__ uint32_t smem_u32(const void* p) {
    uint32_t a;
    asm("{ .reg .u64 t; cvta.to.shared.u64 t, %1; cvt.u32.u64 %0, t; }" : "=r"(a) : "l"(p));
    return a;
}
__device__ __forceinline__ void cpasync16(uint32_t s, const void* g) {
    asm volatile("cp.async.cg.shared.global [%0], [%1], 16;" :: "r"(s), "l"(g) : "memory");
}
__device__ __forceinline__ uint32_t swz(uint32_t off) {        // SW128 XOR swizzle
    return off ^ ((off >> 3) & 0x70);
}
__device__ __forceinline__ void ldsm4(uint32_t* r, uint32_t addr) {
    asm volatile("ldmatrix.sync.aligned.m8n8.x4.shared.b16 {%0,%1,%2,%3}, [%4];"
                 : "=r"(r[0]), "=r"(r[1]), "=r"(r[2]), "=r"(r[3]) : "r"(addr));
}
__device__ __forceinline__ void mma_bf16(float* d, const uint32_t* a, const uint32_t* b) {
    asm volatile(
        "mma.sync.aligned.m16n8k16.row.col.f32.bf16.bf16.f32 "
        "{%0,%1,%2,%3}, {%4,%5,%6,%7}, {%8,%9}, {%0,%1,%2,%3};"
        : "+f"(d[0]), "+f"(d[1]), "+f"(d[2]), "+f"(d[3])
        : "r"(a[0]), "r"(a[1]), "r"(a[2]), "r"(a[3]), "r"(b[0]), "r"(b[1]));
}

// ---------------------------------------------------------------------------
// Split-bf16 conversion: in fp32 [R,K0] -> out bf16 [R,3*K0]
// amode=1 (A side): [hi | hi | lo] ; amode=0 (B side): [hi | lo | hi]
// ---------------------------------------------------------------------------
__global__ void convert_split(const float* __restrict__ in, __nv_bfloat16* __restrict__ out,
                              int n, int amode) {
    int idx = blockIdx.x * 256 + threadIdx.x;
    if (idx >= n) return;
    int r = idx >> 11;          // /K0 (2048)
    int c = idx & (K0 - 1);
    float x = in[idx];
    __nv_bfloat16 hi = __float2bfloat16(x);
    __nv_bfloat16 lo = __float2bfloat16(x - __bfloat162float(hi));
    __nv_bfloat16* orow = out + (size_t)r * KC;
    if (amode) {
        orow[c] = hi; orow[K0 + c] = hi; orow[2 * K0 + c] = lo;
    } else {
        orow[c] = hi; orow[K0 + c] = lo; orow[2 * K0 + c] = hi;
    }
}

// ---------------------------------------------------------------------------
// bf16 HMMA GEMM:  C[bm+128, bn+128] = A' B'^T over KC
// A' [M,KC] bf16 row-major, B' [N,KC] bf16 row-major, C fp32 row-major (ldc)
// CTA 128x128, KB=64, 8 warps (2x4), warp tile 64x32, cp.async double buffer.
// ---------------------------------------------------------------------------
#define KB      64
#define NKB     (KC / KB)         // 96
#define SA_OFF(b) ((b) * 16384)
#define SB_OFF(b) (32768 + (b) * 16384)
#define GEMM_SMEM 65536

__global__ __launch_bounds__(256)
void gemm_mma(const __nv_bfloat16* __restrict__ A, const __nv_bfloat16* __restrict__ B,
              float* __restrict__ C, int ldc) {
    extern __shared__ char dsm[];
    const uint32_t base = smem_u32(dsm);
    const int tid  = threadIdx.x;
    const int wid  = tid >> 5;
    const int lane = tid & 31;
    const int wm   = wid >> 2;          // 0..1
    const int wn   = wid & 3;           // 0..3
    const int quad = lane >> 3;         // 0..3
    const int l8   = lane & 7;
    const int bm = blockIdx.y * 128;
    const int bn = blockIdx.x * 128;

    const __nv_bfloat16* Abase = A + (size_t)bm * KC;
    const __nv_bfloat16* Bbase = B + (size_t)bn * KC;

    float acc[4][4][4];
#pragma unroll
    for (int i = 0; i < 4; i++)
#pragma unroll
        for (int j = 0; j < 4; j++)
#pragma unroll
            for (int v = 0; v < 4; v++) acc[i][j][v] = 0.f;

    // ldmatrix lane geometry
    int a_row[4], b_row[2];
#pragma unroll
    for (int mi = 0; mi < 4; mi++) a_row[mi] = wm * 64 + mi * 16 + (quad & 1) * 8 + l8;
#pragma unroll
    for (int n2 = 0; n2 < 2; n2++) b_row[n2] = wn * 32 + n2 * 16 + (quad >> 1) * 8 + l8;
    const int a_koff = (quad >> 1) * 16;       // bytes
    const int b_koff = (quad & 1) * 16;        // bytes

    // cp.async loader lane geometry: chunk = tid + i*256 ; r=chunk/8, cc=chunk%8
    const int ld_r = tid >> 3;        // base row (stride 32 per iter)
    const int ld_c = (tid & 7) * 8;   // element offset in k (8 elems = 16B)

    auto issue_loads = [&](int kb, int buf) {
        const __nv_bfloat16* ag = Abase + (size_t)ld_r * KC + kb * KB + ld_c;
        const __nv_bfloat16* bg = Bbase + (size_t)ld_r * KC + kb * KB + ld_c;
        uint32_t soff = swz((uint32_t)(ld_r * 128 + ld_c * 2));
#pragma unroll
        for (int i = 0; i < 4; i++) {
            uint32_t s = swz((uint32_t)((ld_r + i * 32) * 128 + ld_c * 2));
            cpasync16(base + SA_OFF(buf) + s, ag + (size_t)i * 32 * KC);
            cpasync16(base + SB_OFF(buf) + s, bg + (size_t)i * 32 * KC);
        }
        (void)soff;
        asm volatile("cp.async.commit_group;" ::: "memory");
    };

    issue_loads(0, 0);

    for (int kb = 0; kb < NKB; kb++) {
        const int buf = kb & 1;
        if (kb + 1 < NKB) {
            issue_loads(kb + 1, buf ^ 1);
            asm volatile("cp.async.wait_group 1;" ::: "memory");
        } else {
            asm volatile("cp.async.wait_group 0;" ::: "memory");
        }
        __syncthreads();

        const uint32_t As = base + SA_OFF(buf);
        const uint32_t Bs = base + SB_OFF(buf);
#pragma unroll
        for (int ks = 0; ks < 4; ks++) {
            uint32_t af[4][4], bf[2][4];
#pragma unroll
            for (int mi = 0; mi < 4; mi++)
                ldsm4(af[mi], As + swz((uint32_t)(a_row[mi] * 128 + ks * 32 + a_koff)));
#pragma unroll
            for (int n2 = 0; n2 < 2; n2++)
                ldsm4(bf[n2], Bs + swz((uint32_t)(b_row[n2] * 128 + ks * 32 + b_koff)));
#pragma unroll
            for (int mi = 0; mi < 4; mi++) {
#pragma unroll
                for (int ni = 0; ni < 4; ni++) {
                    uint32_t bb[2] = { bf[ni >> 1][(ni & 1) * 2], bf[ni >> 1][(ni & 1) * 2 + 1] };
                    mma_bf16(acc[mi][ni], af[mi], bb);
                }
            }
        }
        __syncthreads();
    }

    // epilogue: direct fp32 stores
    const int er = lane >> 2;
    const int ec = (lane & 3) * 2;
#pragma unroll
    for (int mi = 0; mi < 4; mi++) {
        int row0 = bm + wm * 64 + mi * 16 + er;
#pragma unroll
        for (int ni = 0; ni < 4; ni++) {
            int col = bn + wn * 32 + ni * 8 + ec;
            float2 v0 = make_float2(acc[mi][ni][0], acc[mi][ni][1]);
            float2 v1 = make_float2(acc[mi][ni][2], acc[mi][ni][3]);
            *(float2*)(C + (size_t)row0 * ldc + col) = v0;
            *(float2*)(C + (size_t)(row0 + 8) * ldc + col) = v1;
        }
    }
}

// ---------------------------------------------------------------------------
// RoPE in-place on g_qkv. grid (S, NH+NKV), block 64
// ---------------------------------------------------------------------------
__global__ void rope_kernel(float* __restrict__ qkv) {
    const int s = blockIdx.x;
    const int h = blockIdx.y;
    const int i = threadIdx.x;
    const int col = (h < NH) ? h * HD : (HID + (h - NH) * HD);
    float* p = qkv + (size_t)s * QKVW + col;
    float ang = (float)s * powf(10000.0f, -(float)(2 * i) / (float)HD);
    float c = cosf(ang), sn = sinf(ang);
    float x0 = p[i], x1 = p[i + 64];
    p[i]      = x0 * c - x1 * sn;
    p[i + 64] = x1 * c + x0 * sn;
}

// ---------------------------------------------------------------------------
// Flash attention (causal, GQA) — fp32 SIMT (round-3 HMMA target)
// ---------------------------------------------------------------------------
#define FA_SMEM_FLOATS (128*68 + 128*68 + 64*132 + 64*68 + 192)

__global__ __launch_bounds__(256, 1)
void flash_attn_kernel(const float* __restrict__ qkv, float* __restrict__ attn_out) {
    extern __shared__ float sm[];
    float* Qt   = sm;
    float* Kt   = Qt + 128 * 68;
    float* Vs   = Kt + 128 * 68;
    float* Pt   = Vs + 64 * 132;
    float* mrow = Pt + 64 * 68;
    float* lrow = mrow + 64;
    float* srow = lrow + 64;

    const int qb  = blockIdx.x;
    const int h   = blockIdx.y;
    const int tid = threadIdx.x;
    const int tr  = tid >> 4;
    const int tc  = tid & 15;
    const int kvh = h >> 2;
    const int q_col0 = h * HD;
    const int k_col0 = HID + kvh * HD;
    const int v_col0 = HID + KVDIM + kvh * HD;
    const int q_row0 = qb * 64;

    for (int idx = tid; idx < 64 * 32; idx += 256) {
        int r = idx >> 5, c4 = (idx & 31) << 2;
        float4 v = *(const float4*)&qkv[(size_t)(q_row0 + r) * QKVW + q_col0 + c4];
        Qt[(c4 + 0) * 68 + r] = v.x;
        Qt[(c4 + 1) * 68 + r] = v.y;
        Qt[(c4 + 2) * 68 + r] = v.z;
        Qt[(c4 + 3) * 68 + r] = v.w;
    }
    if (tid < 64) { mrow[tid] = -INFINITY; lrow[tid] = 0.f; }

    float o_acc[4][8];
#pragma unroll
    for (int i = 0; i < 4; i++)
#pragma unroll
        for (int j = 0; j < 8; j++) o_acc[i][j] = 0.f;

    const float sscale = 0.08838834764831845f;

    for (int kb = 0; kb <= qb; kb++) {
        __syncthreads();
        for (int idx = tid; idx < 64 * 32; idx += 256) {
            int r = idx >> 5, c4 = (idx & 31) << 2;
            size_t rowoff = (size_t)(kb * 64 + r) * QKVW;
            float4 kv4 = *(const float4*)&qkv[rowoff + k_col0 + c4];
            Kt[(c4 + 0) * 68 + r] = kv4.x;
            Kt[(c4 + 1) * 68 + r] = kv4.y;
            Kt[(c4 + 2) * 68 + r] = kv4.z;
            Kt[(c4 + 3) * 68 + r] = kv4.w;
            float4 vv = *(const float4*)&qkv[rowoff + v_col0 + c4];
            *(float4*)&Vs[r * 132 + c4] = vv;
        }
        __syncthreads();

        float acc[4][4];
#pragma unroll
        for (int i = 0; i < 4; i++)
#pragma unroll
            for (int j = 0; j < 4; j++) acc[i][j] = 0.f;

#pragma unroll 4
        for (int kk = 0; kk < 128; kk++) {
            float a[4], b[4];
            *(float4*)a = *(const float4*)&Qt[kk * 68 + tr * 4];
            *(float4*)b = *(const float4*)&Kt[kk * 68 + tc * 4];
#pragma unroll
            for (int i = 0; i < 4; i++)
#pragma unroll
                for (int j = 0; j < 4; j++) acc[i][j] += a[i] * b[j];
        }

        const bool diag = (kb == qb);
#pragma unroll
        for (int i = 0; i < 4; i++) {
            int grow = q_row0 + tr * 4 + i;
#pragma unroll
            for (int j = 0; j < 4; j++) {
                int gcol = kb * 64 + tc * 4 + j;
                float s = acc[i][j] * sscale;
                if (diag && gcol > grow) s = -1e30f;
                Pt[(tc * 4 + j) * 68 + (tr * 4 + i)] = s;
            }
        }
        __syncthreads();

        {
            int row = tid >> 2, qd = tid & 3;
            float vals[16];
            float lmax = -1e30f;
#pragma unroll
            for (int jj = 0; jj < 16; jj++) {
                vals[jj] = Pt[(qd * 16 + jj) * 68 + row];
                lmax = fmaxf(lmax, vals[jj]);
            }
            lmax = fmaxf(lmax, __shfl_xor_sync(0xffffffffu, lmax, 1));
            lmax = fmaxf(lmax, __shfl_xor_sync(0xffffffffu, lmax, 2));
            float m_old = mrow[row];
            float m_new = fmaxf(m_old, lmax);
            float psum = 0.f;
#pragma unroll
            for (int jj = 0; jj < 16; jj++) {
                float p = __expf(vals[jj] - m_new);
                Pt[(qd * 16 + jj) * 68 + row] = p;
                psum += p;
            }
            psum += __shfl_xor_sync(0xffffffffu, psum, 1);
            psum += __shfl_xor_sync(0xffffffffu, psum, 2);
            if (qd == 0) {
                float sc = __expf(m_old - m_new);
                srow[row] = sc;
                mrow[row] = m_new;
                lrow[row] = lrow[row] * sc + psum;
            }
        }
        __syncthreads();

#pragma unroll
        for (int i = 0; i < 4; i++) {
            float sc = srow[tr * 4 + i];
#pragma unroll
            for (int j = 0; j < 8; j++) o_acc[i][j] *= sc;
        }

#pragma unroll 4
        for (int kk = 0; kk < 64; kk++) {
            float a[4], b[8];
            *(float4*)a = *(const float4*)&Pt[kk * 68 + tr * 4];
            *(float4*)&b[0] = *(const float4*)&Vs[kk * 132 + tc * 8];
            *(float4*)&b[4] = *(const float4*)&Vs[kk * 132 + tc * 8 + 4];
#pragma unroll
            for (int i = 0; i < 4; i++)
#pragma unroll
                for (int j = 0; j < 8; j++) o_acc[i][j] += a[i] * b[j];
        }
    }

#pragma unroll
    for (int i = 0; i < 4; i++) {
        float inv = 1.0f / lrow[tr * 4 + i];
        float* orow = attn_out + (size_t)(q_row0 + tr * 4 + i) * HID + h * HD + tc * 8;
#pragma unroll
        for (int j = 0; j < 8; j += 4) {
            float4 v = make_float4(o_acc[i][j] * inv, o_acc[i][j+1] * inv,
                                   o_acc[i][j+2] * inv, o_acc[i][j+3] * inv);
            *(float4*)(orow + j) = v;
        }
    }
}

// ---------------------------------------------------------------------------
extern "C" void kernel_launch(void* const* d_in, const int* in_sizes, int n_in,
                              void* d_out, int out_size) {
    const float* X  = (const float*)d_in[0];
    const float* Wq = (const float*)d_in[1];
    const float* Wk = (const float*)d_in[2];
    const float* Wv = (const float*)d_in[3];
    const float* Wo = (const float*)d_in[4];
    float* out = (float*)d_out;

    void* p;
    cudaGetSymbolAddress(&p, g_qkv);   float* qkv  = (float*)p;
    cudaGetSymbolAddress(&p, g_attn);  float* attn = (float*)p;
    cudaGetSymbolAddress(&p, g_Xc);    __nv_bfloat16* Xc    = (__nv_bfloat16*)p;
    cudaGetSymbolAddress(&p, g_Wqkvc); __nv_bfloat16* Wqkvc = (__nv_bfloat16*)p;
    cudaGetSymbolAddress(&p, g_Woc);   __nv_bfloat16* Woc   = (__nv_bfloat16*)p;
    cudaGetSymbolAddress(&p, g_attnc); __nv_bfloat16* attnc = (__nv_bfloat16*)p;

    cudaFuncSetAttribute(gemm_mma, cudaFuncAttributeMaxDynamicSharedMemorySize, GEMM_SMEM);
    const size_t fa_smem = FA_SMEM_FLOATS * sizeof(float);
    cudaFuncSetAttribute(flash_attn_kernel,
                         cudaFuncAttributeMaxDynamicSharedMemorySize, (int)fa_smem);

    // split-bf16 conversions
    convert_split<<<(S_LEN * K0 + 255) / 256, 256>>>(X, Xc, S_LEN * K0, 1);
    convert_split<<<(HID * K0 + 255) / 256, 256>>>(Wq, Wqkvc, HID * K0, 0);
    convert_split<<<(KVDIM * K0 + 255) / 256, 256>>>(Wk, Wqkvc + (size_t)HID * KC, KVDIM * K0, 0);
    convert_split<<<(KVDIM * K0 + 255) / 256, 256>>>(Wv, Wqkvc + (size_t)(HID + KVDIM) * KC, KVDIM * K0, 0);
    convert_split<<<(HID * K0 + 255) / 256, 256>>>(Wo, Woc, HID * K0, 0);

    // QKV projection: [2048,3072] = Xc @ Wqkvc^T
    gemm_mma<<<dim3(QKVW / 128, S_LEN / 128), 256, GEMM_SMEM>>>(Xc, Wqkvc, qkv, QKVW);

    // RoPE on Q and K
    rope_kernel<<<dim3(S_LEN, NH + NKV), 64>>>(qkv);

    // Causal GQA flash attention
    flash_attn_kernel<<<dim3(S_LEN / 64, NH), 256, fa_smem>>>(qkv, attn);

    // Output projection
    convert_split<<<(S_LEN * K0 + 255) / 256, 256>>>(attn, attnc, S_LEN * K0, 1);
    gemm_mma<<<dim3(HID / 128, S_LEN / 128), 256, GEMM_SMEM>>>(attnc, Woc, out, HID);
}

// round 4
// speedup vs baseline: 4.0200x; 2.2001x over previous
#include <cuda_runtime.h>
#include <cuda_bf16.h>
#include <math.h>
#include <stdint.h>

// Problem constants
#define S_LEN  2048
#define HID    2048
#define NH     16
#define NKV    4
#define HD     128
#define KVDIM  512
#define QKVW   3072
#define K0     2048
#define KC     (3*K0)      // 6144 split-bf16 concatenated K

// Scratch (device globals — no allocation allowed)
__device__ float g_qkv[S_LEN * QKVW];            // [S][3072]: Q | K | V (fp32)
__device__ float g_attn[S_LEN * HID];            // attention output (fp32)
__device__ __nv_bfloat16 g_Xc[S_LEN * KC];       // X split-cat  [2048,6144]
__device__ __nv_bfloat16 g_Wqkvc[QKVW * KC];     // Wq|Wk|Wv split-cat [3072,6144]
__device__ __nv_bfloat16 g_Woc[HID * KC];        // Wo split-cat [2048,6144]
__device__ __nv_bfloat16 g_attnc[S_LEN * KC];    // attn split-cat
// attention operands (split bf16)
__device__ __nv_bfloat16 g_Qhi[S_LEN * HID];     // scaled q hi
__device__ __nv_bfloat16 g_Qlo[S_LEN * HID];     // scaled q lo
__device__ __nv_bfloat16 g_Khi[S_LEN * KVDIM];
__device__ __nv_bfloat16 g_Klo[S_LEN * KVDIM];
__device__ __nv_bfloat16 g_Vhi[S_LEN * KVDIM];
__device__ __nv_bfloat16 g_Vlo[S_LEN * KVDIM];

// ---------------------------------------------------------------------------
// helpers
// ---------------------------------------------------------------------------
__device__ __forceinline__ uint32_t smem_u32(const void* p) {
    uint32_t a;
    asm("{ .reg .u64 t; cvta.to.shared.u64 t, %1; cvt.u32.u64 %0, t; }" : "=r"(a) : "l"(p));
    return a;
}
__device__ __forceinline__ void cpasync16(uint32_t s, const void* g) {
    asm volatile("cp.async.cg.shared.global [%0], [%1], 16;" :: "r"(s), "l"(g) : "memory");
}
__device__ __forceinline__ uint32_t swz(uint32_t off) {        // SW128 XOR swizzle
    return off ^ ((off >> 3) & 0x70);
}
__device__ __forceinline__ void ldsm4(uint32_t* r, uint32_t addr) {
    asm volatile("ldmatrix.sync.aligned.m8n8.x4.shared.b16 {%0,%1,%2,%3}, [%4];"
                 : "=r"(r[0]), "=r"(r[1]), "=r"(r[2]), "=r"(r[3]) : "r"(addr));
}
__device__ __forceinline__ void ldsm4t(uint32_t* r, uint32_t addr) {
    asm volatile("ldmatrix.sync.aligned.m8n8.x4.trans.shared.b16 {%0,%1,%2,%3}, [%4];"
                 : "=r"(r[0]), "=r"(r[1]), "=r"(r[2]), "=r"(r[3]) : "r"(addr));
}
__device__ __forceinline__ void mma_bf16(float* d, const uint32_t* a, const uint32_t* b) {
    asm volatile(
        "mma.sync.aligned.m16n8k16.row.col.f32.bf16.bf16.f32 "
        "{%0,%1,%2,%3}, {%4,%5,%6,%7}, {%8,%9}, {%0,%1,%2,%3};"
        : "+f"(d[0]), "+f"(d[1]), "+f"(d[2]), "+f"(d[3])
        : "r"(a[0]), "r"(a[1]), "r"(a[2]), "r"(a[3]), "r"(b[0]), "r"(b[1]));
}
__device__ __forceinline__ uint32_t pack_bf16(float lo, float hi) {
    __nv_bfloat162 t = __floats2bfloat162_rn(lo, hi);   // x=lo(low half), y=hi
    return *reinterpret_cast<uint32_t*>(&t);
}

// ---------------------------------------------------------------------------
// Split-bf16 conversion: in fp32 [R,K0] -> out bf16 [R,3*K0]
// amode=1 (A side): [hi | hi | lo] ; amode=0 (B side): [hi | lo | hi]
// ---------------------------------------------------------------------------
__global__ void convert_split(const float* __restrict__ in, __nv_bfloat16* __restrict__ out,
                              int n, int amode) {
    int idx = blockIdx.x * 256 + threadIdx.x;
    if (idx >= n) return;
    int r = idx >> 11;
    int c = idx & (K0 - 1);
    float x = in[idx];
    __nv_bfloat16 hi = __float2bfloat16(x);
    __nv_bfloat16 lo = __float2bfloat16(x - __bfloat162float(hi));
    __nv_bfloat16* orow = out + (size_t)r * KC;
    if (amode) {
        orow[c] = hi; orow[K0 + c] = hi; orow[2 * K0 + c] = lo;
    } else {
        orow[c] = hi; orow[K0 + c] = lo; orow[2 * K0 + c] = hi;
    }
}

// ---------------------------------------------------------------------------
// Convert rope'd qkv (fp32) into split attention operands. sscale folded into Q.
// ---------------------------------------------------------------------------
__global__ void convert_qkv(const float* __restrict__ qkv,
                            __nv_bfloat16* __restrict__ Qh, __nv_bfloat16* __restrict__ Ql,
                            __nv_bfloat16* __restrict__ Kh, __nv_bfloat16* __restrict__ Kl,
                            __nv_bfloat16* __restrict__ Vh, __nv_bfloat16* __restrict__ Vl) {
    int idx = blockIdx.x * 256 + threadIdx.x;
    if (idx >= S_LEN * QKVW) return;
    int s = idx / QKVW, c = idx - s * QKVW;
    float x = qkv[idx];
    if (c < HID) x *= 0.08838834764831845f;      // 1/sqrt(128)
    __nv_bfloat16 hi = __float2bfloat16(x);
    __nv_bfloat16 lo = __float2bfloat16(x - __bfloat162float(hi));
    if (c < HID) {
        Qh[(size_t)s * HID + c] = hi; Ql[(size_t)s * HID + c] = lo;
    } else if (c < HID + KVDIM) {
        int cc = c - HID;
        Kh[(size_t)s * KVDIM + cc] = hi; Kl[(size_t)s * KVDIM + cc] = lo;
    } else {
        int cc = c - HID - KVDIM;
        Vh[(size_t)s * KVDIM + cc] = hi; Vl[(size_t)s * KVDIM + cc] = lo;
    }
}

// ---------------------------------------------------------------------------
// bf16 HMMA GEMM:  C[bm+128, bn+128] = A' B'^T over KC  (unchanged from R3)
// ---------------------------------------------------------------------------
#define KB      64
#define NKB     (KC / KB)
#define SA_OFF(b) ((b) * 16384)
#define SB_OFF(b) (32768 + (b) * 16384)
#define GEMM_SMEM 65536

__global__ __launch_bounds__(256)
void gemm_mma(const __nv_bfloat16* __restrict__ A, const __nv_bfloat16* __restrict__ B,
              float* __restrict__ C, int ldc) {
    extern __shared__ char dsm[];
    const uint32_t base = smem_u32(dsm);
    const int tid  = threadIdx.x;
    const int wid  = tid >> 5;
    const int lane = tid & 31;
    const int wm   = wid >> 2;
    const int wn   = wid & 3;
    const int quad = lane >> 3;
    const int l8   = lane & 7;
    const int bm = blockIdx.y * 128;
    const int bn = blockIdx.x * 128;

    const __nv_bfloat16* Abase = A + (size_t)bm * KC;
    const __nv_bfloat16* Bbase = B + (size_t)bn * KC;

    float acc[4][4][4];
#pragma unroll
    for (int i = 0; i < 4; i++)
#pragma unroll
        for (int j = 0; j < 4; j++)
#pragma unroll
            for (int v = 0; v < 4; v++) acc[i][j][v] = 0.f;

    int a_row[4], b_row[2];
#pragma unroll
    for (int mi = 0; mi < 4; mi++) a_row[mi] = wm * 64 + mi * 16 + (quad & 1) * 8 + l8;
#pragma unroll
    for (int n2 = 0; n2 < 2; n2++) b_row[n2] = wn * 32 + n2 * 16 + (quad >> 1) * 8 + l8;
    const int a_koff = (quad >> 1) * 16;
    const int b_koff = (quad & 1) * 16;

    const int ld_r = tid >> 3;
    const int ld_c = (tid & 7) * 8;

    auto issue_loads = [&](int kb, int buf) {
        const __nv_bfloat16* ag = Abase + (size_t)ld_r * KC + kb * KB + ld_c;
        const __nv_bfloat16* bg = Bbase + (size_t)ld_r * KC + kb * KB + ld_c;
#pragma unroll
        for (int i = 0; i < 4; i++) {
            uint32_t s = swz((uint32_t)((ld_r + i * 32) * 128 + ld_c * 2));
            cpasync16(base + SA_OFF(buf) + s, ag + (size_t)i * 32 * KC);
            cpasync16(base + SB_OFF(buf) + s, bg + (size_t)i * 32 * KC);
        }
        asm volatile("cp.async.commit_group;" ::: "memory");
    };

    issue_loads(0, 0);

    for (int kb = 0; kb < NKB; kb++) {
        const int buf = kb & 1;
        if (kb + 1 < NKB) {
            issue_loads(kb + 1, buf ^ 1);
            asm volatile("cp.async.wait_group 1;" ::: "memory");
        } else {
            asm volatile("cp.async.wait_group 0;" ::: "memory");
        }
        __syncthreads();

        const uint32_t As = base + SA_OFF(buf);
        const uint32_t Bs = base + SB_OFF(buf);
#pragma unroll
        for (int ks = 0; ks < 4; ks++) {
            uint32_t af[4][4], bf[2][4];
#pragma unroll
            for (int mi = 0; mi < 4; mi++)
                ldsm4(af[mi], As + swz((uint32_t)(a_row[mi] * 128 + ks * 32 + a_koff)));
#pragma unroll
            for (int n2 = 0; n2 < 2; n2++)
                ldsm4(bf[n2], Bs + swz((uint32_t)(b_row[n2] * 128 + ks * 32 + b_koff)));
#pragma unroll
            for (int mi = 0; mi < 4; mi++) {
#pragma unroll
                for (int ni = 0; ni < 4; ni++) {
                    uint32_t bb[2] = { bf[ni >> 1][(ni & 1) * 2], bf[ni >> 1][(ni & 1) * 2 + 1] };
                    mma_bf16(acc[mi][ni], af[mi], bb);
                }
            }
        }
        __syncthreads();
    }

    const int er = lane >> 2;
    const int ec = (lane & 3) * 2;
#pragma unroll
    for (int mi = 0; mi < 4; mi++) {
        int row0 = bm + wm * 64 + mi * 16 + er;
#pragma unroll
        for (int ni = 0; ni < 4; ni++) {
            int col = bn + wn * 32 + ni * 8 + ec;
            float2 v0 = make_float2(acc[mi][ni][0], acc[mi][ni][1]);
            float2 v1 = make_float2(acc[mi][ni][2], acc[mi][ni][3]);
            *(float2*)(C + (size_t)row0 * ldc + col) = v0;
            *(float2*)(C + (size_t)(row0 + 8) * ldc + col) = v1;
        }
    }
}

// ---------------------------------------------------------------------------
// RoPE in-place on g_qkv.
// ---------------------------------------------------------------------------
__global__ void rope_kernel(float* __restrict__ qkv) {
    const int s = blockIdx.x;
    const int h = blockIdx.y;
    const int i = threadIdx.x;
    const int col = (h < NH) ? h * HD : (HID + (h - NH) * HD);
    float* p = qkv + (size_t)s * QKVW + col;
    float ang = (float)s * powf(10000.0f, -(float)(2 * i) / (float)HD);
    float c = cosf(ang), sn = sinf(ang);
    float x0 = p[i], x1 = p[i + 64];
    p[i]      = x0 * c - x1 * sn;
    p[i + 64] = x1 * c + x0 * sn;
}

// ---------------------------------------------------------------------------
// HMMA flash attention (causal, GQA), split-bf16 3-term compensation.
// CTA = (q-tile of 128, head). 8 warps x 16 rows. KV tiles of 64, double buffer.
// smem: Qhi 32K | Qlo 32K | 2 x (Khi,Klo,Vhi,Vlo 16K each)  = 192KB
// Layout: panels of 64 cols (128B rows), SW128 swizzle within panel.
// ---------------------------------------------------------------------------
#define QHI_OFF 0
#define QLO_OFF 32768
#define KVB_OFF(b) (65536 + (b) * 65536)
#define KHI_O 0
#define KLO_O 16384
#define VHI_O 32768
#define VLO_O 49152
#define FLASH_SMEM 196608

__global__ __launch_bounds__(256)
void flash_mma(const __nv_bfloat16* __restrict__ Qh, const __nv_bfloat16* __restrict__ Ql,
               const __nv_bfloat16* __restrict__ Kh, const __nv_bfloat16* __restrict__ Kl,
               const __nv_bfloat16* __restrict__ Vh, const __nv_bfloat16* __restrict__ Vl,
               float* __restrict__ attn_out) {
    extern __shared__ char dsm[];
    const uint32_t base = smem_u32(dsm);
    const int tid  = threadIdx.x;
    const int lane = tid & 31;
    const int warp = tid >> 5;
    const int qi   = (int)gridDim.x - 1 - (int)blockIdx.x;   // big tiles first
    const int h    = blockIdx.y;
    const int kvh  = h >> 2;
    const int wrow = warp * 16;
    const int nt   = 2 * qi + 2;

    // ---- initial loads: Q (both) + KV tile 0 into buf 0 ----
    {
        const int rr = tid >> 4;
        const int cc = (tid & 15) * 8;
        const int panel = cc >> 6;
        const int col = cc & 63;
        const __nv_bfloat16* qh = Qh + (size_t)(qi * 128) * HID + h * HD + cc;
        const __nv_bfloat16* ql = Ql + (size_t)(qi * 128) * HID + h * HD + cc;
#pragma unroll
        for (int i = 0; i < 8; i++) {
            int r = rr + i * 16;
            uint32_t d = panel * 16384 + swz((uint32_t)(r * 128 + col * 2));
            cpasync16(base + QHI_OFF + d, qh + (size_t)r * HID);
            cpasync16(base + QLO_OFF + d, ql + (size_t)r * HID);
        }
    }
    auto issue_kv = [&](int kb, int buf) {
        const int rr = tid >> 4;
        const int cc = (tid & 15) * 8;
        const int panel = cc >> 6;
        const int col = cc & 63;
        const uint32_t kvb = base + KVB_OFF(buf);
#pragma unroll
        for (int i = 0; i < 4; i++) {
            int r = rr + i * 16;
            uint32_t d = panel * 8192 + swz((uint32_t)(r * 128 + col * 2));
            size_t g = (size_t)(kb * 64 + r) * KVDIM + kvh * HD + cc;
            cpasync16(kvb + KHI_O + d, Kh + g);
            cpasync16(kvb + KLO_O + d, Kl + g);
            cpasync16(kvb + VHI_O + d, Vh + g);
            cpasync16(kvb + VLO_O + d, Vl + g);
        }
        asm volatile("cp.async.commit_group;" ::: "memory");
    };
    issue_kv(0, 0);
    asm volatile("cp.async.wait_group 0;" ::: "memory");
    __syncthreads();

    // fragment loaders
    auto ldQ = [&](uint32_t arr, int ks, uint32_t* a) {
        int row = wrow + (lane & 15);
        int kc = (16 * ks) & 63;
        uint32_t addr = base + arr + (ks >> 2) * 16384 +
                        swz((uint32_t)(row * 128 + (kc + (lane >> 4) * 8) * 2));
        ldsm4(a, addr);
    };
    auto ldK = [&](uint32_t arr, int ks, int nb, uint32_t* b) {
        int row = nb * 16 + (lane & 7) + ((lane >> 4) << 3);
        int kc = (16 * ks) & 63;
        int kadd = ((lane >> 3) & 1) * 8;
        uint32_t addr = base + arr + (ks >> 2) * 8192 +
                        swz((uint32_t)(row * 128 + (kc + kadd) * 2));
        ldsm4(b, addr);
    };
    auto ldV = [&](uint32_t arr, int ks, int db, uint32_t* b) {
        int row = ks * 16 + (lane & 7) + (((lane >> 3) & 1) << 3);
        int dc = (16 * db) & 63;
        int dadd = (lane >> 4) * 8;
        uint32_t addr = base + arr + (db >> 2) * 8192 +
                        swz((uint32_t)(row * 128 + (dc + dadd) * 2));
        ldsm4t(b, addr);
    };

    float oacc[16][4];
#pragma unroll
    for (int i = 0; i < 16; i++)
#pragma unroll
        for (int v = 0; v < 4; v++) oacc[i][v] = 0.f;
    float ml[2] = {-1e30f, -1e30f};
    float ll[2] = {0.f, 0.f};

    for (int kb = 0; kb < nt; kb++) {
        const int buf = kb & 1;
        if (kb + 1 < nt) {
            issue_kv(kb + 1, buf ^ 1);
            asm volatile("cp.async.wait_group 1;" ::: "memory");
        } else {
            asm volatile("cp.async.wait_group 0;" ::: "memory");
        }
        __syncthreads();

        const uint32_t kvb = KVB_OFF(buf);

        // ---- scores: 3-term split QK^T ----
        float pacc[8][4];
#pragma unroll
        for (int i = 0; i < 8; i++)
#pragma unroll
            for (int v = 0; v < 4; v++) pacc[i][v] = 0.f;

#pragma unroll
        for (int ks = 0; ks < 8; ks++) {
            uint32_t aqh[4], aql[4];
            ldQ(QHI_OFF, ks, aqh);
            ldQ(QLO_OFF, ks, aql);
#pragma unroll
            for (int nb = 0; nb < 4; nb++) {
                uint32_t bh[4], bl[4];
                ldK(kvb + KHI_O, ks, nb, bh);
                ldK(kvb + KLO_O, ks, nb, bl);
                mma_bf16(pacc[2 * nb],     aqh, bh);
                mma_bf16(pacc[2 * nb + 1], aqh, bh + 2);
                mma_bf16(pacc[2 * nb],     aqh, bl);
                mma_bf16(pacc[2 * nb + 1], aqh, bl + 2);
                mma_bf16(pacc[2 * nb],     aql, bh);
                mma_bf16(pacc[2 * nb + 1], aql, bh + 2);
            }
        }

        // ---- causal mask (diagonal tiles only) ----
        if (kb >= 2 * qi) {
            int r0 = qi * 128 + wrow + (lane >> 2);
#pragma unroll
            for (int ni = 0; ni < 8; ni++) {
                int c0 = kb * 64 + ni * 8 + (lane & 3) * 2;
                if (c0     > r0)     pacc[ni][0] = -1e30f;
                if (c0 + 1 > r0)     pacc[ni][1] = -1e30f;
                if (c0     > r0 + 8) pacc[ni][2] = -1e30f;
                if (c0 + 1 > r0 + 8) pacc[ni][3] = -1e30f;
            }
        }

        // ---- online softmax ----
        float mx0 = -1e30f, mx1 = -1e30f;
#pragma unroll
        for (int ni = 0; ni < 8; ni++) {
            mx0 = fmaxf(mx0, fmaxf(pacc[ni][0], pacc[ni][1]));
            mx1 = fmaxf(mx1, fmaxf(pacc[ni][2], pacc[ni][3]));
        }
        mx0 = fmaxf(mx0, __shfl_xor_sync(0xffffffffu, mx0, 1));
        mx0 = fmaxf(mx0, __shfl_xor_sync(0xffffffffu, mx0, 2));
        mx1 = fmaxf(mx1, __shfl_xor_sync(0xffffffffu, mx1, 1));
        mx1 = fmaxf(mx1, __shfl_xor_sync(0xffffffffu, mx1, 2));
        float mn0 = fmaxf(ml[0], mx0);
        float mn1 = fmaxf(ml[1], mx1);
        float sc0 = __expf(ml[0] - mn0);
        float sc1 = __expf(ml[1] - mn1);

        uint32_t phi[16], plo[16];
        float ps0 = 0.f, ps1 = 0.f;
#pragma unroll
        for (int ni = 0; ni < 8; ni++) {
            float p0 = __expf(pacc[ni][0] - mn0);
            float p1 = __expf(pacc[ni][1] - mn0);
            float p2 = __expf(pacc[ni][2] - mn1);
            float p3 = __expf(pacc[ni][3] - mn1);
            ps0 += p0 + p1;
            ps1 += p2 + p3;
            __nv_bfloat16 h0 = __float2bfloat16(p0), h1 = __float2bfloat16(p1);
            __nv_bfloat16 h2 = __float2bfloat16(p2), h3 = __float2bfloat16(p3);
            phi[2 * ni]     = pack_bf16(__bfloat162float(h0), __bfloat162float(h1));
            phi[2 * ni + 1] = pack_bf16(__bfloat162float(h2), __bfloat162float(h3));
            plo[2 * ni]     = pack_bf16(p0 - __bfloat162float(h0), p1 - __bfloat162float(h1));
            plo[2 * ni + 1] = pack_bf16(p2 - __bfloat162float(h2), p3 - __bfloat162float(h3));
        }
        ps0 += __shfl_xor_sync(0xffffffffu, ps0, 1);
        ps0 += __shfl_xor_sync(0xffffffffu, ps0, 2);
        ps1 += __shfl_xor_sync(0xffffffffu, ps1, 1);
        ps1 += __shfl_xor_sync(0xffffffffu, ps1, 2);
        ll[0] = ll[0] * sc0 + ps0;
        ll[1] = ll[1] * sc1 + ps1;
        ml[0] = mn0; ml[1] = mn1;
#pragma unroll
        for (int ni = 0; ni < 16; ni++) {
            oacc[ni][0] *= sc0; oacc[ni][1] *= sc0;
            oacc[ni][2] *= sc1; oacc[ni][3] *= sc1;
        }

        // ---- O += P V (3-term split) ----
        // Note A-frag layout: C(m16n8) frag pairs map directly to A(m16k16):
        // a0,a1 = frags 2ks ; a2,a3 = frag 2ks+1 (regs: [c0c1],[c2c3]).
#pragma unroll
        for (int ks = 0; ks < 4; ks++) {
            uint32_t aph[4] = { phi[4 * ks], phi[4 * ks + 1], phi[4 * ks + 2], phi[4 * ks + 3] };
            uint32_t apl[4] = { plo[4 * ks], plo[4 * ks + 1], plo[4 * ks + 2], plo[4 * ks + 3] };
#pragma unroll
            for (int db = 0; db < 8; db++) {
                uint32_t bh[4], bl[4];
                ldV(kvb + VHI_O, ks, db, bh);
                mma_bf16(oacc[2 * db],     aph, bh);
                mma_bf16(oacc[2 * db + 1], aph, bh + 2);
                mma_bf16(oacc[2 * db],     apl, bh);
                mma_bf16(oacc[2 * db + 1], apl, bh + 2);
                ldV(kvb + VLO_O, ks, db, bl);
                mma_bf16(oacc[2 * db],     aph, bl);
                mma_bf16(oacc[2 * db + 1], aph, bl + 2);
            }
        }
        __syncthreads();
    }

    // ---- epilogue ----
    float inv0 = 1.0f / ll[0];
    float inv1 = 1.0f / ll[1];
    int row0 = qi * 128 + wrow + (lane >> 2);
#pragma unroll
    for (int ni = 0; ni < 16; ni++) {
        int col = h * HD + ni * 8 + (lane & 3) * 2;
        float2 v0 = make_float2(oacc[ni][0] * inv0, oacc[ni][1] * inv0);
        float2 v1 = make_float2(oacc[ni][2] * inv1, oacc[ni][3] * inv1);
        *(float2*)(attn_out + (size_t)row0 * HID + col) = v0;
        *(float2*)(attn_out + (size_t)(row0 + 8) * HID + col) = v1;
    }
}

// ---------------------------------------------------------------------------
extern "C" void kernel_launch(void* const* d_in, const int* in_sizes, int n_in,
                              void* d_out, int out_size) {
    const float* X  = (const float*)d_in[0];
    const float* Wq = (const float*)d_in[1];
    const float* Wk = (const float*)d_in[2];
    const float* Wv = (const float*)d_in[3];
    const float* Wo = (const float*)d_in[4];
    float* out = (float*)d_out;

    void* p;
    cudaGetSymbolAddress(&p, g_qkv);   float* qkv  = (float*)p;
    cudaGetSymbolAddress(&p, g_attn);  float* attn = (float*)p;
    cudaGetSymbolAddress(&p, g_Xc);    __nv_bfloat16* Xc    = (__nv_bfloat16*)p;
    cudaGetSymbolAddress(&p, g_Wqkvc); __nv_bfloat16* Wqkvc = (__nv_bfloat16*)p;
    cudaGetSymbolAddress(&p, g_Woc);   __nv_bfloat16* Woc   = (__nv_bfloat16*)p;
    cudaGetSymbolAddress(&p, g_attnc); __nv_bfloat16* attnc = (__nv_bfloat16*)p;
    __nv_bfloat16 *Qh, *Ql, *Kh, *Kl, *Vh, *Vl;
    cudaGetSymbolAddress(&p, g_Qhi); Qh = (__nv_bfloat16*)p;
    cudaGetSymbolAddress(&p, g_Qlo); Ql = (__nv_bfloat16*)p;
    cudaGetSymbolAddress(&p, g_Khi); Kh = (__nv_bfloat16*)p;
    cudaGetSymbolAddress(&p, g_Klo); Kl = (__nv_bfloat16*)p;
    cudaGetSymbolAddress(&p, g_Vhi); Vh = (__nv_bfloat16*)p;
    cudaGetSymbolAddress(&p, g_Vlo); Vl = (__nv_bfloat16*)p;

    cudaFuncSetAttribute(gemm_mma, cudaFuncAttributeMaxDynamicSharedMemorySize, GEMM_SMEM);
    cudaFuncSetAttribute(flash_mma, cudaFuncAttributeMaxDynamicSharedMemorySize, FLASH_SMEM);

    // split-bf16 conversions (weights + input)
    convert_split<<<(S_LEN * K0 + 255) / 256, 256>>>(X, Xc, S_LEN * K0, 1);
    convert_split<<<(HID * K0 + 255) / 256, 256>>>(Wq, Wqkvc, HID * K0, 0);
    convert_split<<<(KVDIM * K0 + 255) / 256, 256>>>(Wk, Wqkvc + (size_t)HID * KC, KVDIM * K0, 0);
    convert_split<<<(KVDIM * K0 + 255) / 256, 256>>>(Wv, Wqkvc + (size_t)(HID + KVDIM) * KC, KVDIM * K0, 0);
    convert_split<<<(HID * K0 + 255) / 256, 256>>>(Wo, Woc, HID * K0, 0);

    // QKV projection
    gemm_mma<<<dim3(QKVW / 128, S_LEN / 128), 256, GEMM_SMEM>>>(Xc, Wqkvc, qkv, QKVW);

    // RoPE
    rope_kernel<<<dim3(S_LEN, NH + NKV), 64>>>(qkv);

    // split conversion for attention operands (sscale folded into Q)
    convert_qkv<<<(S_LEN * QKVW + 255) / 256, 256>>>(qkv, Qh, Ql, Kh, Kl, Vh, Vl);

    // HMMA causal flash attention
    flash_mma<<<dim3(S_LEN / 128, NH), 256, FLASH_SMEM>>>(Qh, Ql, Kh, Kl, Vh, Vl, attn);

    // Output projection
    convert_split<<<(S_LEN * K0 + 255) / 256, 256>>>(attn, attnc, S_LEN * K0, 1);
    gemm_mma<<<dim3(HID / 128, S_LEN / 128), 256, GEMM_SMEM>>>(attnc, Woc, out, HID);
}

// round 6
// speedup vs baseline: 5.5131x; 1.3714x over previous
#include <cuda_runtime.h>
#include <cuda_fp16.h>
#include <math.h>
#include <stdint.h>

// Problem constants
#define S_LEN  2048
#define HID    2048
#define NH     16
#define NKV    4
#define HD     128
#define KVDIM  512
#define QKVW   3072
#define K0     2048
#define KC2    (2*K0)      // 4096: B-side hi|lo concatenated K

// Scratch (device globals — no allocation allowed)
__device__ float  g_qkv[S_LEN * QKVW];           // [S][3072]: Q | K | V (fp32)
__device__ __half g_attnh[S_LEN * HID];          // attention output (fp16, A-side)
__device__ __half g_Xh[S_LEN * K0];              // X rounded fp16
__device__ __half g_Wqkv2[QKVW * KC2];           // Wq|Wk|Wv  [3072][hi|lo 4096]
__device__ __half g_Wo2[HID * KC2];              // Wo [2048][hi|lo 4096]
// attention operands
__device__ __half g_Qh[S_LEN * HID];             // scaled+rope q, rounded
__device__ __half g_Khi[S_LEN * KVDIM];
__device__ __half g_Klo[S_LEN * KVDIM];
__device__ __half g_Vhi[S_LEN * KVDIM];
__device__ __half g_Vlo[S_LEN * KVDIM];

// ---------------------------------------------------------------------------
// helpers
// ---------------------------------------------------------------------------
__device__ __forceinline__ uint32_t smem_u32(const void* p) {
    uint32_t a;
    asm("{ .reg .u64 t; cvta.to.shared.u64 t, %1; cvt.u32.u64 %0, t; }" : "=r"(a) : "l"(p));
    return a;
}
__device__ __forceinline__ void cpasync16(uint32_t s, const void* g) {
    asm volatile("cp.async.cg.shared.global [%0], [%1], 16;" :: "r"(s), "l"(g) : "memory");
}
__device__ __forceinline__ uint32_t swz(uint32_t off) {        // SW128 XOR swizzle
    return off ^ ((off >> 3) & 0x70);
}
__device__ __forceinline__ void ldsm4(uint32_t* r, uint32_t addr) {
    asm volatile("ldmatrix.sync.aligned.m8n8.x4.shared.b16 {%0,%1,%2,%3}, [%4];"
                 : "=r"(r[0]), "=r"(r[1]), "=r"(r[2]), "=r"(r[3]) : "r"(addr));
}
__device__ __forceinline__ void ldsm4t(uint32_t* r, uint32_t addr) {
    asm volatile("ldmatrix.sync.aligned.m8n8.x4.trans.shared.b16 {%0,%1,%2,%3}, [%4];"
                 : "=r"(r[0]), "=r"(r[1]), "=r"(r[2]), "=r"(r[3]) : "r"(addr));
}
__device__ __forceinline__ void mma_f16(float* d, const uint32_t* a, const uint32_t* b) {
    asm volatile(
        "mma.sync.aligned.m16n8k16.row.col.f32.f16.f16.f32 "
        "{%0,%1,%2,%3}, {%4,%5,%6,%7}, {%8,%9}, {%0,%1,%2,%3};"
        : "+f"(d[0]), "+f"(d[1]), "+f"(d[2]), "+f"(d[3])
        : "r"(a[0]), "r"(a[1]), "r"(a[2]), "r"(a[3]), "r"(b[0]), "r"(b[1]));
}
__device__ __forceinline__ uint32_t pack_h2(float lo, float hi) {
    __half2 t = __floats2half2_rn(lo, hi);
    return *reinterpret_cast<uint32_t*>(&t);
}

// ---------------------------------------------------------------------------
// Conversions
// ---------------------------------------------------------------------------
// A-side: plain fp16 rounding
__global__ void convert_a(const float* __restrict__ in, __half* __restrict__ out, int n) {
    int idx = blockIdx.x * 256 + threadIdx.x;
    if (idx < n) out[idx] = __float2half(in[idx]);
}
// B-side: split hi|lo concatenated along K: out[r][c]=hi, out[r][2048+c]=lo
__global__ void convert_w2(const float* __restrict__ in, __half* __restrict__ out, int n) {
    int idx = blockIdx.x * 256 + threadIdx.x;
    if (idx >= n) return;
    int r = idx >> 11;
    int c = idx & (K0 - 1);
    float x = in[idx];
    __half hi = __float2half(x);
    __half lo = __float2half(x - __half2float(hi));
    out[(size_t)r * KC2 + c] = hi;
    out[(size_t)r * KC2 + K0 + c] = lo;
}
// Fused RoPE + split/round into attention operands. grid (S, 24), block 64.
// h 0..15: Q heads (rope + scale, round). 16..19: K heads (rope, split).
// 20..23: V heads (split).
__global__ void convert_qkv_rope(const float* __restrict__ qkv,
                                 __half* __restrict__ Qh,
                                 __half* __restrict__ Kh, __half* __restrict__ Kl,
                                 __half* __restrict__ Vh, __half* __restrict__ Vl) {
    const int s = blockIdx.x;
    const int h = blockIdx.y;
    const int i = threadIdx.x;       // 0..63
    const float sscale = 0.08838834764831845f;
    if (h < NH) {
        const float* p = qkv + (size_t)s * QKVW + h * HD;
        float ang = (float)s * powf(10000.0f, -(float)(2 * i) / (float)HD);
        float c = cosf(ang), sn = sinf(ang);
        float x0 = p[i], x1 = p[i + 64];
        float y0 = (x0 * c - x1 * sn) * sscale;
        float y1 = (x1 * c + x0 * sn) * sscale;
        __half* q = Qh + (size_t)s * HID + h * HD;
        q[i] = __float2half(y0);
        q[i + 64] = __float2half(y1);
    } else if (h < NH + NKV) {
        const int kh = h - NH;
        const float* p = qkv + (size_t)s * QKVW + HID + kh * HD;
        float ang = (float)s * powf(10000.0f, -(float)(2 * i) / (float)HD);
        float c = cosf(ang), sn = sinf(ang);
        float x0 = p[i], x1 = p[i + 64];
        float y0 = x0 * c - x1 * sn;
        float y1 = x1 * c + x0 * sn;
        size_t o = (size_t)s * KVDIM + kh * HD;
        __half h0 = __float2half(y0), h1 = __float2half(y1);
        Kh[o + i] = h0;       Kl[o + i] = __float2half(y0 - __half2float(h0));
        Kh[o + i + 64] = h1;  Kl[o + i + 64] = __float2half(y1 - __half2float(h1));
    } else {
        const int vh = h - NH - NKV;
        const float* p = qkv + (size_t)s * QKVW + HID + KVDIM + vh * HD;
        float x0 = p[i], x1 = p[i + 64];
        size_t o = (size_t)s * KVDIM + vh * HD;
        __half h0 = __float2half(x0), h1 = __float2half(x1);
        Vh[o + i] = h0;       Vl[o + i] = __float2half(x0 - __half2float(h0));
        Vh[o + i + 64] = h1;  Vl[o + i + 64] = __float2half(x1 - __half2float(h1));
    }
}

// ---------------------------------------------------------------------------
// fp16 HMMA GEMM, 2-term B-split:  C[bm+128, bn+128] = A B'^T over KC2=4096,
// where A column wraps mod K0 (A' = [A|A] implicitly).
// A [M,K0] fp16 row-major, B' [N,KC2] fp16 row-major, C fp32 (ldc).
// CTA 128x128, KB=64, 8 warps (2x4) warp tile 64x32, 3-stage cp.async pipeline.
// ---------------------------------------------------------------------------
#define KB      64
#define NKB     (KC2 / KB)        // 64
#define SA_OFF(b) ((b) * 32768)
#define SB_OFF(b) ((b) * 32768 + 16384)
#define GEMM_SMEM 98304

__global__ __launch_bounds__(256)
void gemm_mma(const __half* __restrict__ A, const __half* __restrict__ B,
              float* __restrict__ C, int ldc) {
    extern __shared__ char dsm[];
    const uint32_t base = smem_u32(dsm);
    const int tid  = threadIdx.x;
    const int wid  = tid >> 5;
    const int lane = tid & 31;
    const int wm   = wid >> 2;
    const int wn   = wid & 3;
    const int quad = lane >> 3;
    const int l8   = lane & 7;
    const int bm = blockIdx.y * 128;
    const int bn = blockIdx.x * 128;

    const __half* Abase = A + (size_t)bm * K0;
    const __half* Bbase = B + (size_t)bn * KC2;

    float acc[4][4][4];
#pragma unroll
    for (int i = 0; i < 4; i++)
#pragma unroll
        for (int j = 0; j < 4; j++)
#pragma unroll
            for (int v = 0; v < 4; v++) acc[i][j][v] = 0.f;

    int a_row[4], b_row[2];
#pragma unroll
    for (int mi = 0; mi < 4; mi++) a_row[mi] = wm * 64 + mi * 16 + (quad & 1) * 8 + l8;
#pragma unroll
    for (int n2 = 0; n2 < 2; n2++) b_row[n2] = wn * 32 + n2 * 16 + (quad >> 1) * 8 + l8;
    const int a_koff = (quad >> 1) * 16;
    const int b_koff = (quad & 1) * 16;

    const int ld_r = tid >> 3;
    const int ld_c = (tid & 7) * 8;

    auto issue_loads = [&](int kb, int buf) {
        const int a_col = (kb & 31) * KB + ld_c;     // wrap A over K0
        const __half* ag = Abase + (size_t)ld_r * K0 + a_col;
        const __half* bg = Bbase + (size_t)ld_r * KC2 + kb * KB + ld_c;
#pragma unroll
        for (int i = 0; i < 4; i++) {
            uint32_t s = swz((uint32_t)((ld_r + i * 32) * 128 + ld_c * 2));
            cpasync16(base + SA_OFF(buf) + s, ag + (size_t)i * 32 * K0);
            cpasync16(base + SB_OFF(buf) + s, bg + (size_t)i * 32 * KC2);
        }
        asm volatile("cp.async.commit_group;" ::: "memory");
    };

    issue_loads(0, 0);
    issue_loads(1, 1);

    for (int kb = 0; kb < NKB; kb++) {
        const int buf = kb % 3;
        if (kb + 2 < NKB) {
            issue_loads(kb + 2, (kb + 2) % 3);
            asm volatile("cp.async.wait_group 2;" ::: "memory");
        } else if (kb + 1 < NKB) {
            asm volatile("cp.async.wait_group 1;" ::: "memory");
        } else {
            asm volatile("cp.async.wait_group 0;" ::: "memory");
        }
        __syncthreads();

        const uint32_t As = base + SA_OFF(buf);
        const uint32_t Bs = base + SB_OFF(buf);
#pragma unroll
        for (int ks = 0; ks < 4; ks++) {
            uint32_t af[4][4], bf[2][4];
#pragma unroll
            for (int mi = 0; mi < 4; mi++)
                ldsm4(af[mi], As + swz((uint32_t)(a_row[mi] * 128 + ks * 32 + a_koff)));
#pragma unroll
            for (int n2 = 0; n2 < 2; n2++)
                ldsm4(bf[n2], Bs + swz((uint32_t)(b_row[n2] * 128 + ks * 32 + b_koff)));
#pragma unroll
            for (int mi = 0; mi < 4; mi++) {
#pragma unroll
                for (int ni = 0; ni < 4; ni++) {
                    uint32_t bb[2] = { bf[ni >> 1][(ni & 1) * 2], bf[ni >> 1][(ni & 1) * 2 + 1] };
                    mma_f16(acc[mi][ni], af[mi], bb);
                }
            }
        }
        __syncthreads();
    }

    const int er = lane >> 2;
    const int ec = (lane & 3) * 2;
#pragma unroll
    for (int mi = 0; mi < 4; mi++) {
        int row0 = bm + wm * 64 + mi * 16 + er;
#pragma unroll
        for (int ni = 0; ni < 4; ni++) {
            int col = bn + wn * 32 + ni * 8 + ec;
            float2 v0 = make_float2(acc[mi][ni][0], acc[mi][ni][1]);
            float2 v1 = make_float2(acc[mi][ni][2], acc[mi][ni][3]);
            *(float2*)(C + (size_t)row0 * ldc + col) = v0;
            *(float2*)(C + (size_t)(row0 + 8) * ldc + col) = v1;
        }
    }
}

// ---------------------------------------------------------------------------
// HMMA flash attention (causal, GQA), fp16 2-term (K,V split; Q,P rounded).
// CTA = (q-tile 128, head). 8 warps x 16 rows. KV tiles of 64, double buffer.
// smem: Q 32K | 2 x (Khi,Klo,Vhi,Vlo 16K each) = 160KB
// ---------------------------------------------------------------------------
#define Q_OFF 0
#define KVB_OFF(b) (32768 + (b) * 65536)
#define KHI_O 0
#define KLO_O 16384
#define VHI_O 32768
#define VLO_O 49152
#define FLASH_SMEM 163840

__global__ __launch_bounds__(256)
void flash_mma(const __half* __restrict__ Qp,
               const __half* __restrict__ Kh, const __half* __restrict__ Kl,
               const __half* __restrict__ Vh, const __half* __restrict__ Vl,
               __half* __restrict__ attn_out) {
    extern __shared__ char dsm[];
    const uint32_t base = smem_u32(dsm);
    const int tid  = threadIdx.x;
    const int lane = tid & 31;
    const int warp = tid >> 5;
    const int qi   = (int)gridDim.x - 1 - (int)blockIdx.x;   // big tiles first
    const int h    = blockIdx.y;
    const int kvh  = h >> 2;
    const int wrow = warp * 16;
    const int nt   = 2 * qi + 2;

    // ---- initial loads: Q + KV tile 0 ----
    {
        const int rr = tid >> 4;
        const int cc = (tid & 15) * 8;
        const int panel = cc >> 6;
        const int col = cc & 63;
        const __half* qg = Qp + (size_t)(qi * 128) * HID + h * HD + cc;
#pragma unroll
        for (int i = 0; i < 8; i++) {
            int r = rr + i * 16;
            uint32_t d = panel * 16384 + swz((uint32_t)(r * 128 + col * 2));
            cpasync16(base + Q_OFF + d, qg + (size_t)r * HID);
        }
    }
    auto issue_kv = [&](int kb, int buf) {
        const int rr = tid >> 4;
        const int cc = (tid & 15) * 8;
        const int panel = cc >> 6;
        const int col = cc & 63;
        const uint32_t kvb = base + KVB_OFF(buf);
#pragma unroll
        for (int i = 0; i < 4; i++) {
            int r = rr + i * 16;
            uint32_t d = panel * 8192 + swz((uint32_t)(r * 128 + col * 2));
            size_t g = (size_t)(kb * 64 + r) * KVDIM + kvh * HD + cc;
            cpasync16(kvb + KHI_O + d, Kh + g);
            cpasync16(kvb + KLO_O + d, Kl + g);
            cpasync16(kvb + VHI_O + d, Vh + g);
            cpasync16(kvb + VLO_O + d, Vl + g);
        }
        asm volatile("cp.async.commit_group;" ::: "memory");
    };
    issue_kv(0, 0);
    asm volatile("cp.async.wait_group 0;" ::: "memory");
    __syncthreads();

    auto ldQ = [&](int ks, uint32_t* a) {
        int row = wrow + (lane & 15);
        int kc = (16 * ks) & 63;
        uint32_t addr = base + Q_OFF + (ks >> 2) * 16384 +
                        swz((uint32_t)(row * 128 + (kc + (lane >> 4) * 8) * 2));
        ldsm4(a, addr);
    };
    auto ldK = [&](uint32_t arr, int ks, int nb, uint32_t* b) {
        int row = nb * 16 + (lane & 7) + ((lane >> 4) << 3);
        int kc = (16 * ks) & 63;
        int kadd = ((lane >> 3) & 1) * 8;
        uint32_t addr = base + arr + (ks >> 2) * 8192 +
                        swz((uint32_t)(row * 128 + (kc + kadd) * 2));
        ldsm4(b, addr);
    };
    auto ldV = [&](uint32_t arr, int ks, int db, uint32_t* b) {
        int row = ks * 16 + (lane & 7) + (((lane >> 3) & 1) << 3);
        int dc = (16 * db) & 63;
        int dadd = (lane >> 4) * 8;
        uint32_t addr = base + arr + (db >> 2) * 8192 +
                        swz((uint32_t)(row * 128 + (dc + dadd) * 2));
        ldsm4t(b, addr);
    };

    float oacc[16][4];
#pragma unroll
    for (int i = 0; i < 16; i++)
#pragma unroll
        for (int v = 0; v < 4; v++) oacc[i][v] = 0.f;
    float ml[2] = {-1e30f, -1e30f};
    float ll[2] = {0.f, 0.f};

    for (int kb = 0; kb < nt; kb++) {
        const int buf = kb & 1;
        if (kb + 1 < nt) {
            issue_kv(kb + 1, buf ^ 1);
            asm volatile("cp.async.wait_group 1;" ::: "memory");
        } else {
            asm volatile("cp.async.wait_group 0;" ::: "memory");
        }
        __syncthreads();

        const uint32_t kvb = KVB_OFF(buf);

        // ---- scores: Q·Kh + Q·Kl ----
        float pacc[8][4];
#pragma unroll
        for (int i = 0; i < 8; i++)
#pragma unroll
            for (int v = 0; v < 4; v++) pacc[i][v] = 0.f;

#pragma unroll
        for (int ks = 0; ks < 8; ks++) {
            uint32_t aq[4];
            ldQ(ks, aq);
#pragma unroll
            for (int nb = 0; nb < 4; nb++) {
                uint32_t bh[4], bl[4];
                ldK(kvb + KHI_O, ks, nb, bh);
                ldK(kvb + KLO_O, ks, nb, bl);
                mma_f16(pacc[2 * nb],     aq, bh);
                mma_f16(pacc[2 * nb + 1], aq, bh + 2);
                mma_f16(pacc[2 * nb],     aq, bl);
                mma_f16(pacc[2 * nb + 1], aq, bl + 2);
            }
        }

        // ---- causal mask (diagonal tiles only) ----
        if (kb >= 2 * qi) {
            int r0 = qi * 128 + wrow + (lane >> 2);
#pragma unroll
            for (int ni = 0; ni < 8; ni++) {
                int c0 = kb * 64 + ni * 8 + (lane & 3) * 2;
                if (c0     > r0)     pacc[ni][0] = -1e30f;
                if (c0 + 1 > r0)     pacc[ni][1] = -1e30f;
                if (c0     > r0 + 8) pacc[ni][2] = -1e30f;
                if (c0 + 1 > r0 + 8) pacc[ni][3] = -1e30f;
            }
        }

        // ---- online softmax ----
        float mx0 = -1e30f, mx1 = -1e30f;
#pragma unroll
        for (int ni = 0; ni < 8; ni++) {
            mx0 = fmaxf(mx0, fmaxf(pacc[ni][0], pacc[ni][1]));
            mx1 = fmaxf(mx1, fmaxf(pacc[ni][2], pacc[ni][3]));
        }
        mx0 = fmaxf(mx0, __shfl_xor_sync(0xffffffffu, mx0, 1));
        mx0 = fmaxf(mx0, __shfl_xor_sync(0xffffffffu, mx0, 2));
        mx1 = fmaxf(mx1, __shfl_xor_sync(0xffffffffu, mx1, 1));
        mx1 = fmaxf(mx1, __shfl_xor_sync(0xffffffffu, mx1, 2));
        float mn0 = fmaxf(ml[0], mx0);
        float mn1 = fmaxf(ml[1], mx1);
        float sc0 = __expf(ml[0] - mn0);
        float sc1 = __expf(ml[1] - mn1);

        uint32_t phi[16];
        float ps0 = 0.f, ps1 = 0.f;
#pragma unroll
        for (int ni = 0; ni < 8; ni++) {
            float p0 = __expf(pacc[ni][0] - mn0);
            float p1 = __expf(pacc[ni][1] - mn0);
            float p2 = __expf(pacc[ni][2] - mn1);
            float p3 = __expf(pacc[ni][3] - mn1);
            ps0 += p0 + p1;
            ps1 += p2 + p3;
            phi[2 * ni]     = pack_h2(p0, p1);
            phi[2 * ni + 1] = pack_h2(p2, p3);
        }
        ps0 += __shfl_xor_sync(0xffffffffu, ps0, 1);
        ps0 += __shfl_xor_sync(0xffffffffu, ps0, 2);
        ps1 += __shfl_xor_sync(0xffffffffu, ps1, 1);
        ps1 += __shfl_xor_sync(0xffffffffu, ps1, 2);
        ll[0] = ll[0] * sc0 + ps0;
        ll[1] = ll[1] * sc1 + ps1;
        ml[0] = mn0; ml[1] = mn1;
#pragma unroll
        for (int ni = 0; ni < 16; ni++) {
            oacc[ni][0] *= sc0; oacc[ni][1] *= sc0;
            oacc[ni][2] *= sc1; oacc[ni][3] *= sc1;
        }

        // ---- O += P·Vh + P·Vl ----
#pragma unroll
        for (int ks = 0; ks < 4; ks++) {
            uint32_t aph[4] = { phi[4 * ks], phi[4 * ks + 1], phi[4 * ks + 2], phi[4 * ks + 3] };
#pragma unroll
            for (int db = 0; db < 8; db++) {
                uint32_t bh[4], bl[4];
                ldV(kvb + VHI_O, ks, db, bh);
                mma_f16(oacc[2 * db],     aph, bh);
                mma_f16(oacc[2 * db + 1], aph, bh + 2);
                ldV(kvb + VLO_O, ks, db, bl);
                mma_f16(oacc[2 * db],     aph, bl);
                mma_f16(oacc[2 * db + 1], aph, bl + 2);
            }
        }
        __syncthreads();
    }

    // ---- epilogue: write fp16 (A-side of O projection) ----
    float inv0 = 1.0f / ll[0];
    float inv1 = 1.0f / ll[1];
    int row0 = qi * 128 + wrow + (lane >> 2);
#pragma unroll
    for (int ni = 0; ni < 16; ni++) {
        int col = h * HD + ni * 8 + (lane & 3) * 2;
        __half2 v0 = __floats2half2_rn(oacc[ni][0] * inv0, oacc[ni][1] * inv0);
        __half2 v1 = __floats2half2_rn(oacc[ni][2] * inv1, oacc[ni][3] * inv1);
        *(__half2*)(attn_out + (size_t)row0 * HID + col) = v0;
        *(__half2*)(attn_out + (size_t)(row0 + 8) * HID + col) = v1;
    }
}

// ---------------------------------------------------------------------------
extern "C" void kernel_launch(void* const* d_in, const int* in_sizes, int n_in,
                              void* d_out, int out_size) {
    const float* X  = (const float*)d_in[0];
    const float* Wq = (const float*)d_in[1];
    const float* Wk = (const float*)d_in[2];
    const float* Wv = (const float*)d_in[3];
    const float* Wo = (const float*)d_in[4];
    float* out = (float*)d_out;

    void* p;
    cudaGetSymbolAddress(&p, g_qkv);    float*  qkv   = (float*)p;
    cudaGetSymbolAddress(&p, g_attnh);  __half* attnh = (__half*)p;
    cudaGetSymbolAddress(&p, g_Xh);     __half* Xh    = (__half*)p;
    cudaGetSymbolAddress(&p, g_Wqkv2);  __half* Wqkv2 = (__half*)p;
    cudaGetSymbolAddress(&p, g_Wo2);    __half* Wo2   = (__half*)p;
    __half *Qh, *Kh, *Kl, *Vh, *Vl;
    cudaGetSymbolAddress(&p, g_Qh);  Qh = (__half*)p;
    cudaGetSymbolAddress(&p, g_Khi); Kh = (__half*)p;
    cudaGetSymbolAddress(&p, g_Klo); Kl = (__half*)p;
    cudaGetSymbolAddress(&p, g_Vhi); Vh = (__half*)p;
    cudaGetSymbolAddress(&p, g_Vlo); Vl = (__half*)p;

    cudaFuncSetAttribute(gemm_mma, cudaFuncAttributeMaxDynamicSharedMemorySize, GEMM_SMEM);
    cudaFuncSetAttribute(flash_mma, cudaFuncAttributeMaxDynamicSharedMemorySize, FLASH_SMEM);

    // conversions
    convert_a<<<(S_LEN * K0 + 255) / 256, 256>>>(X, Xh, S_LEN * K0);
    convert_w2<<<(HID * K0 + 255) / 256, 256>>>(Wq, Wqkv2, HID * K0);
    convert_w2<<<(KVDIM * K0 + 255) / 256, 256>>>(Wk, Wqkv2 + (size_t)HID * KC2, KVDIM * K0);
    convert_w2<<<(KVDIM * K0 + 255) / 256, 256>>>(Wv, Wqkv2 + (size_t)(HID + KVDIM) * KC2, KVDIM * K0);
    convert_w2<<<(HID * K0 + 255) / 256, 256>>>(Wo, Wo2, HID * K0);

    // QKV projection
    gemm_mma<<<dim3(QKVW / 128, S_LEN / 128), 256, GEMM_SMEM>>>(Xh, Wqkv2, qkv, QKVW);

    // fused RoPE + split conversion
    convert_qkv_rope<<<dim3(S_LEN, NH + 2 * NKV), 64>>>(qkv, Qh, Kh, Kl, Vh, Vl);

    // HMMA causal flash attention -> fp16
    flash_mma<<<dim3(S_LEN / 128, NH), 256, FLASH_SMEM>>>(Qh, Kh, Kl, Vh, Vl, attnh);

    // Output projection
    gemm_mma<<<dim3(HID / 128, S_LEN / 128), 256, GEMM_SMEM>>>(attnh, Wo2, out, HID);
}